// round 1
// baseline (speedup 1.0000x reference)
#include <cuda_runtime.h>
#include <cuda_bf16.h>

#define T_DIM 8192
#define K_DIM 2048
#define TM1   (T_DIM - 1)                     // 8191 rows in the loss
#define NTOT  ((long long)TM1 * K_DIM)        // 16,775,168 elements
#define GAMMA 0.99f

#define THREADS      256
#define SCAN_BLOCKS  8                        // 8 * 256 = 2048 columns
#define QSUM_BLOCKS  448
#define NBLOCKS      (SCAN_BLOCKS + QSUM_BLOCKS)

// Scratch (device globals are the allowed scratch mechanism)
__device__ float  g_decay[(long long)TM1 * K_DIM];
__device__ float  g_pd   [(long long)TM1 * K_DIM];   // td * decay
__device__ double g_part [NBLOCKS];

__device__ __forceinline__ float sl1(float pred, float target) {
    float d  = pred - target;
    float ad = fabsf(d);
    return (ad < 1.0f) ? (0.5f * d * d) : (ad - 0.5f);
}

__global__ void __launch_bounds__(THREADS)
retrace_main(const float* __restrict__ q,
             const float* __restrict__ tq,
             const float* __restrict__ tv,
             const float* __restrict__ r,
             const float* __restrict__ olp,
             const float* __restrict__ tlp)
{
    double acc = 0.0;

    if (blockIdx.x < SCAN_BLOCKS) {
        // ------- per-column scan: one thread per column (coalesced along k) -------
        const int k = blockIdx.x * THREADS + threadIdx.x;

        // Forward: decay cumprod + p = td*decay, stop once the whole warp's
        // decay has underflowed to exactly 0 (then all later retrace == 0,
        // matching the reference's clamped division exactly).
        float decay = 1.0f;
        int   tstop = TM1;   // first t with decay == 0 (exclusive bound of active region)
        for (int t = 0; t < TM1; ++t) {
            float o   = olp[t + 1];                       // warp-uniform broadcast
            float liw = tlp[(size_t)(t + 1) * K_DIM + k] - o;
            float iw  = expf(fminf(liw, 0.0f));
            decay     = decay * (GAMMA * iw);
            float tdv = r[(size_t)t * K_DIM + k]
                      + GAMMA * (tv[(size_t)(t + 1) * K_DIM + k]
                                 - iw * tq[(size_t)(t + 1) * K_DIM + k]);
            g_decay[(size_t)t * K_DIM + k] = decay;
            g_pd   [(size_t)t * K_DIM + k] = tdv * decay;
            if (decay == 0.0f && tstop == TM1) tstop = t;
            if (__all_sync(0xFFFFFFFFu, decay == 0.0f)) break;
        }

        // Warp max of tstop so the backward loop is warp-uniform.
        int tmax = tstop;
        #pragma unroll
        for (int off = 16; off > 0; off >>= 1)
            tmax = max(tmax, __shfl_xor_sync(0xFFFFFFFFu, tmax, off));

        // Backward: reverse cumsum of p, clamped division, loss correction
        // relative to sl1(q, 0) which the q-sum blocks cover globally.
        float R = 0.0f;
        for (int t = tmax - 1; t >= 0; --t) {
            if (t < tstop) {
                float dec  = g_decay[(size_t)t * K_DIM + k];
                R         += g_pd   [(size_t)t * K_DIM + k];
                float retr = R / fmaxf(dec, 1e-10f);
                float qv   = q[(size_t)t * K_DIM + k];
                acc += (double)(sl1(qv, retr) - sl1(qv, 0.0f));
            }
        }
    } else {
        // ------- elementwise sum of sl1(q, 0) over q[0 : TM1*K), vectorized -------
        const long long nvec   = NTOT / 4;                 // divisible: K%4==0
        const float4*   q4     = (const float4*)q;
        long long       idx    = (long long)(blockIdx.x - SCAN_BLOCKS) * THREADS + threadIdx.x;
        const long long stride = (long long)QSUM_BLOCKS * THREADS;
        float fa = 0.0f;
        for (; idx < nvec; idx += stride) {
            float4 v = q4[idx];
            fa += sl1(v.x, 0.0f) + sl1(v.y, 0.0f) + sl1(v.z, 0.0f) + sl1(v.w, 0.0f);
        }
        acc = (double)fa;
    }

    // Deterministic block reduction (fixed shared-memory tree order)
    __shared__ double sh[THREADS];
    sh[threadIdx.x] = acc;
    __syncthreads();
    #pragma unroll
    for (int s = THREADS / 2; s > 0; s >>= 1) {
        if (threadIdx.x < s) sh[threadIdx.x] += sh[threadIdx.x + s];
        __syncthreads();
    }
    if (threadIdx.x == 0) g_part[blockIdx.x] = sh[0];
}

__global__ void __launch_bounds__(THREADS)
retrace_finalize(float* __restrict__ out)
{
    __shared__ double sh[THREADS];
    double a = 0.0;
    for (int i = threadIdx.x; i < NBLOCKS; i += THREADS) a += g_part[i];
    sh[threadIdx.x] = a;
    __syncthreads();
    #pragma unroll
    for (int s = THREADS / 2; s > 0; s >>= 1) {
        if (threadIdx.x < s) sh[threadIdx.x] += sh[threadIdx.x + s];
        __syncthreads();
    }
    if (threadIdx.x == 0) out[0] = (float)(sh[0] / (double)NTOT);
}

extern "C" void kernel_launch(void* const* d_in, const int* in_sizes, int n_in,
                              void* d_out, int out_size)
{
    const float* q   = (const float*)d_in[0];  // state_trajectory_action_values (T,K)
    const float* tq  = (const float*)d_in[1];  // target_state_trajectory_action_values (T,K)
    const float* tv  = (const float*)d_in[2];  // target_expected_state_values (T,K)
    const float* r   = (const float*)d_in[3];  // rewards (T,K)
    const float* olp = (const float*)d_in[4];  // original_log_trajectory_action_probs (T,)
    const float* tlp = (const float*)d_in[5];  // target_log_trajectory_task_action_probs (T,K)
    float* out = (float*)d_out;

    retrace_main<<<NBLOCKS, THREADS>>>(q, tq, tv, r, olp, tlp);
    retrace_finalize<<<1, THREADS>>>(out);
}

// round 2
// speedup vs baseline: 2.3227x; 2.3227x over previous
#include <cuda_runtime.h>
#include <cuda_bf16.h>

#define T_DIM 8192
#define K_DIM 2048
#define TM1   (T_DIM - 1)                     // 8191 rows in the loss
#define NTOT  ((long long)TM1 * K_DIM)        // 16,775,168 elements
#define GAMMA 0.99f

#define BATCH        8
#define NB           (TM1 / BATCH)            // 1023 full batches (tail = 7 rows)
#define SCAN_BLOCKS  64                       // 64 blocks * 32 thr = 2048 columns
#define QSUM_BLOCKS  2368                     // ~16 one-warp blocks per SM
#define NBLOCKS      (SCAN_BLOCKS + QSUM_BLOCKS)

// Scratch (device globals are the allowed scratch mechanism)
__device__ float  g_decay[(long long)TM1 * K_DIM];
__device__ float  g_pd   [(long long)TM1 * K_DIM];   // td * decay
__device__ double g_part [NBLOCKS];

__device__ __forceinline__ float sl1(float pred, float target) {
    float d  = pred - target;
    float ad = fabsf(d);
    return (ad < 1.0f) ? (0.5f * d * d) : (ad - 0.5f);
}

__global__ void __launch_bounds__(32)
retrace_main(const float* __restrict__ q,
             const float* __restrict__ tq,
             const float* __restrict__ tv,
             const float* __restrict__ r,
             const float* __restrict__ olp,
             const float* __restrict__ tlp)
{
    double acc = 0.0;

    if (blockIdx.x < SCAN_BLOCKS) {
        // ---------------- per-column scan, one warp per 32 columns ----------------
        const int k = blockIdx.x * 32 + threadIdx.x;

        float liwB[2][BATCH], rB[2][BATCH], tvB[2][BATCH], tqB[2][BATCH];

        // prefetch one batch of 8 rows into buffer `buf`
        auto load_batch = [&](int buf, int t0) {
            #pragma unroll
            for (int j = 0; j < BATCH; ++j) {
                int t = t0 + j;
                liwB[buf][j] = tlp[(size_t)(t + 1) * K_DIM + k] - __ldg(&olp[t + 1]);
                rB  [buf][j] = r  [(size_t)t       * K_DIM + k];
                tvB [buf][j] = tv [(size_t)(t + 1) * K_DIM + k];
                tqB [buf][j] = tq [(size_t)(t + 1) * K_DIM + k];
            }
        };

        float decay = 1.0f;
        int   tstop = TM1;            // first t with decay == 0 (exclusive active bound)
        bool  alldead = false;

        load_batch(0, 0);
        int b = 0;
        for (; b < NB; ++b) {
            if (b + 1 < NB) load_batch((b + 1) & 1, (b + 1) * BATCH);  // prefetch next
            const int buf = b & 1;
            #pragma unroll
            for (int j = 0; j < BATCH; ++j) {
                const int t  = b * BATCH + j;
                float iw  = expf(fminf(liwB[buf][j], 0.0f));
                decay     = decay * (GAMMA * iw);
                float tdv = rB[buf][j] + GAMMA * (tvB[buf][j] - iw * tqB[buf][j]);
                g_decay[(size_t)t * K_DIM + k] = decay;
                g_pd   [(size_t)t * K_DIM + k] = tdv * decay;
                if (decay == 0.0f && tstop == TM1) tstop = t;
            }
            if (__all_sync(0xFFFFFFFFu, decay == 0.0f)) { alldead = true; break; }
        }
        // tail rows (8184..8190) — only reached if no column in the warp died
        if (!alldead) {
            for (int t = NB * BATCH; t < TM1; ++t) {
                float liw = tlp[(size_t)(t + 1) * K_DIM + k] - olp[t + 1];
                float iw  = expf(fminf(liw, 0.0f));
                decay     = decay * (GAMMA * iw);
                float tdv = r[(size_t)t * K_DIM + k]
                          + GAMMA * (tv[(size_t)(t + 1) * K_DIM + k]
                                     - iw * tq[(size_t)(t + 1) * K_DIM + k]);
                g_decay[(size_t)t * K_DIM + k] = decay;
                g_pd   [(size_t)t * K_DIM + k] = tdv * decay;
                if (decay == 0.0f && tstop == TM1) tstop = t;
            }
        }

        // warp-uniform backward bound
        int tmax = tstop;
        #pragma unroll
        for (int off = 16; off > 0; off >>= 1)
            tmax = max(tmax, __shfl_xor_sync(0xFFFFFFFFu, tmax, off));

        // --------- backward: reverse cumsum + clamped division, batched loads ---------
        // Rows in [tstop, tmax): pd==0 and decay==0 -> retr==0 -> correction exactly 0,
        // so no per-thread predicate is needed.
        float R = 0.0f;
        int   t = tmax;
        {
            int rem = t % BATCH;          // top partial batch first
            if (rem) {
                int t0 = t - rem;
                float Dd[BATCH], Pp[BATCH], Qq[BATCH];
                #pragma unroll
                for (int j = 0; j < BATCH; ++j) if (j < rem) {
                    Dd[j] = g_decay[(size_t)(t0 + j) * K_DIM + k];
                    Pp[j] = g_pd   [(size_t)(t0 + j) * K_DIM + k];
                    Qq[j] = q      [(size_t)(t0 + j) * K_DIM + k];
                }
                #pragma unroll
                for (int j = BATCH - 1; j >= 0; --j) if (j < rem) {
                    R += Pp[j];
                    float retr = R / fmaxf(Dd[j], 1e-10f);
                    acc += (double)(sl1(Qq[j], retr) - sl1(Qq[j], 0.0f));
                }
                t = t0;
            }
        }
        while (t > 0) {
            int t0 = t - BATCH;
            float Dd[BATCH], Pp[BATCH], Qq[BATCH];
            #pragma unroll
            for (int j = 0; j < BATCH; ++j) {
                Dd[j] = g_decay[(size_t)(t0 + j) * K_DIM + k];
                Pp[j] = g_pd   [(size_t)(t0 + j) * K_DIM + k];
                Qq[j] = q      [(size_t)(t0 + j) * K_DIM + k];
            }
            #pragma unroll
            for (int j = BATCH - 1; j >= 0; --j) {
                R += Pp[j];
                float retr = R / fmaxf(Dd[j], 1e-10f);
                acc += (double)(sl1(Qq[j], retr) - sl1(Qq[j], 0.0f));
            }
            t = t0;
        }
    } else {
        // ------- elementwise sum of sl1(q, 0) over q[0 : TM1*K), vectorized -------
        const long long nvec   = NTOT / 4;                 // divisible: K%4==0
        const float4*   q4     = (const float4*)q;
        long long       idx    = (long long)(blockIdx.x - SCAN_BLOCKS) * 32 + threadIdx.x;
        const long long stride = (long long)QSUM_BLOCKS * 32;
        float fa = 0.0f;
        for (; idx < nvec; idx += stride) {
            float4 v = q4[idx];
            fa += sl1(v.x, 0.0f) + sl1(v.y, 0.0f) + sl1(v.z, 0.0f) + sl1(v.w, 0.0f);
        }
        acc = (double)fa;
    }

    // deterministic warp reduction (fixed shuffle tree)
    #pragma unroll
    for (int off = 16; off > 0; off >>= 1)
        acc += __shfl_xor_sync(0xFFFFFFFFu, acc, off);
    if (threadIdx.x == 0) g_part[blockIdx.x] = acc;
}

__global__ void __launch_bounds__(256)
retrace_finalize(float* __restrict__ out)
{
    __shared__ double sh[256];
    double a = 0.0;
    for (int i = threadIdx.x; i < NBLOCKS; i += 256) a += g_part[i];
    sh[threadIdx.x] = a;
    __syncthreads();
    #pragma unroll
    for (int s = 128; s > 0; s >>= 1) {
        if (threadIdx.x < s) sh[threadIdx.x] += sh[threadIdx.x + s];
        __syncthreads();
    }
    if (threadIdx.x == 0) out[0] = (float)(sh[0] / (double)NTOT);
}

extern "C" void kernel_launch(void* const* d_in, const int* in_sizes, int n_in,
                              void* d_out, int out_size)
{
    const float* q   = (const float*)d_in[0];  // state_trajectory_action_values (T,K)
    const float* tq  = (const float*)d_in[1];  // target_state_trajectory_action_values (T,K)
    const float* tv  = (const float*)d_in[2];  // target_expected_state_values (T,K)
    const float* r   = (const float*)d_in[3];  // rewards (T,K)
    const float* olp = (const float*)d_in[4];  // original_log_trajectory_action_probs (T,)
    const float* tlp = (const float*)d_in[5];  // target_log_trajectory_task_action_probs (T,K)
    float* out = (float*)d_out;

    retrace_main<<<NBLOCKS, 32>>>(q, tq, tv, r, olp, tlp);
    retrace_finalize<<<1, 256>>>(out);
}

// round 3
// speedup vs baseline: 2.7696x; 1.1924x over previous
#include <cuda_runtime.h>
#include <cuda_bf16.h>

#define T_DIM 8192
#define K_DIM 2048
#define TM1   (T_DIM - 1)                      // 8191 rows in the loss
#define NTOT  ((long long)TM1 * K_DIM)         // 16,775,168 elements
#define GAMMA 0.99f

#define BATCH        8
#define NB           (TM1 / BATCH)             // 1023 full batches (tail = 7 rows)
#define SCAN_BLOCKS  64                        // 64 blocks * 32 thr = 2048 columns
#define QSUM_BLOCKS  2368                      // ~16 one-warp blocks per SM
#define NBLOCKS      (SCAN_BLOCKS + QSUM_BLOCKS)

// Scratch (device globals are the allowed scratch mechanism). Zero-initialized
// at module load; rows beyond a warp's written range stay 0 across replays and
// contribute exactly 0 to the correction, so no per-row predicate is needed.
__device__ float2       g_dp  [(long long)TM1 * K_DIM];  // {decay, td*decay}
__device__ double       g_part[NBLOCKS];
__device__ unsigned int g_done;                          // zero-init; self-resetting

__device__ __forceinline__ float sl1(float pred, float target) {
    float d  = pred - target;
    float ad = fabsf(d);
    return (ad < 1.0f) ? (0.5f * d * d) : (ad - 0.5f);
}

__global__ void __launch_bounds__(32)
retrace_main(const float* __restrict__ q,
             const float* __restrict__ tq,
             const float* __restrict__ tv,
             const float* __restrict__ r,
             const float* __restrict__ olp,
             const float* __restrict__ tlp,
             float* __restrict__ out)
{
    double acc = 0.0;

    if (blockIdx.x < SCAN_BLOCKS) {
        // ---------------- per-column scan, one warp per 32 columns ----------------
        const int k = blockIdx.x * 32 + threadIdx.x;

        float decay = 1.0f;
        int   tstop = TM1;               // first t with decay == 0 (exclusive bound)
        bool  dead  = false;

        // ---- forward: register-resident double buffering (static indices) ----
        auto fload = [&](float (&LIW)[BATCH], float (&RR)[BATCH],
                         float (&TV)[BATCH],  float (&TQ)[BATCH], int bb) {
            const int t0 = bb * BATCH;
            #pragma unroll
            for (int j = 0; j < BATCH; ++j) {
                const int t = t0 + j;
                LIW[j] = tlp[(size_t)(t + 1) * K_DIM + k] - __ldg(&olp[t + 1]);
                RR [j] = r  [(size_t)t       * K_DIM + k];
                TV [j] = tv [(size_t)(t + 1) * K_DIM + k];
                TQ [j] = tq [(size_t)(t + 1) * K_DIM + k];
            }
        };
        auto fcomp = [&](float (&LIW)[BATCH], float (&RR)[BATCH],
                         float (&TV)[BATCH],  float (&TQ)[BATCH], int bb) {
            const int t0 = bb * BATCH;
            #pragma unroll
            for (int j = 0; j < BATCH; ++j) {
                float iw  = expf(fminf(LIW[j], 0.0f));
                decay     = decay * (GAMMA * iw);
                float tdv = RR[j] + GAMMA * (TV[j] - iw * TQ[j]);
                g_dp[(size_t)(t0 + j) * K_DIM + k] = make_float2(decay, tdv * decay);
                if (decay == 0.0f && tstop == TM1) tstop = t0 + j;
            }
        };

        {
            float liwA[BATCH], rA[BATCH], tvA[BATCH], tqA[BATCH];
            float liwB[BATCH], rB[BATCH], tvB[BATCH], tqB[BATCH];
            fload(liwA, rA, tvA, tqA, 0);
            int b = 0;
            while (true) {
                if (b + 1 < NB) fload(liwB, rB, tvB, tqB, b + 1);
                fcomp(liwA, rA, tvA, tqA, b);
                if (__all_sync(0xFFFFFFFFu, decay == 0.0f)) { dead = true; break; }
                if (++b >= NB) break;
                if (b + 1 < NB) fload(liwA, rA, tvA, tqA, b + 1);
                fcomp(liwB, rB, tvB, tqB, b);
                if (__all_sync(0xFFFFFFFFu, decay == 0.0f)) { dead = true; break; }
                if (++b >= NB) break;
            }
        }
        // tail rows 8184..8190 — reached only if the warp never fully died
        if (!dead) {
            for (int t = NB * BATCH; t < TM1; ++t) {
                float liw = tlp[(size_t)(t + 1) * K_DIM + k] - olp[t + 1];
                float iw  = expf(fminf(liw, 0.0f));
                decay     = decay * (GAMMA * iw);
                float tdv = r[(size_t)t * K_DIM + k]
                          + GAMMA * (tv[(size_t)(t + 1) * K_DIM + k]
                                     - iw * tq[(size_t)(t + 1) * K_DIM + k]);
                g_dp[(size_t)t * K_DIM + k] = make_float2(decay, tdv * decay);
                if (decay == 0.0f && tstop == TM1) tstop = t;
            }
        }

        // warp-uniform backward bound
        int tmax = tstop;
        #pragma unroll
        for (int off = 16; off > 0; off >>= 1)
            tmax = max(tmax, __shfl_xor_sync(0xFFFFFFFFu, tmax, off));

        // ---- backward: reverse cumsum + clamped division, double-buffered ----
        float R = 0.0f;
        // scalar pre-loop for tail rows if the warp reached them
        if (tmax > NB * BATCH) {
            for (int t = TM1 - 1; t >= NB * BATCH; --t) {
                float2 dp  = g_dp[(size_t)t * K_DIM + k];
                R         += dp.y;
                float retr = R / fmaxf(dp.x, 1e-10f);
                float qv   = q[(size_t)t * K_DIM + k];
                acc += (double)(sl1(qv, retr) - sl1(qv, 0.0f));
            }
            tmax = NB * BATCH;
        }
        const int nbk = (tmax + BATCH - 1) / BATCH;   // full batches cover [0, nbk*8)

        auto bload = [&](float (&D)[BATCH], float (&P)[BATCH], float (&Q)[BATCH], int bb) {
            const int t0 = bb * BATCH;
            #pragma unroll
            for (int j = 0; j < BATCH; ++j) {
                float2 dp = g_dp[(size_t)(t0 + j) * K_DIM + k];
                D[j] = dp.x; P[j] = dp.y;
                Q[j] = q[(size_t)(t0 + j) * K_DIM + k];
            }
        };
        auto bcomp = [&](float (&D)[BATCH], float (&P)[BATCH], float (&Q)[BATCH]) {
            #pragma unroll
            for (int j = BATCH - 1; j >= 0; --j) {
                R += P[j];
                float retr = R / fmaxf(D[j], 1e-10f);
                acc += (double)(sl1(Q[j], retr) - sl1(Q[j], 0.0f));
            }
        };

        if (nbk > 0) {
            float DA[BATCH], PA[BATCH], QA[BATCH];
            float DB[BATCH], PB[BATCH], QB[BATCH];
            int b = nbk - 1;
            bload(DA, PA, QA, b);
            while (true) {
                if (b > 0) bload(DB, PB, QB, b - 1);
                bcomp(DA, PA, QA);
                if (--b < 0) break;
                if (b > 0) bload(DA, PA, QA, b - 1);
                bcomp(DB, PB, QB);
                if (--b < 0) break;
            }
        }
    } else {
        // ------- elementwise sum of sl1(q, 0) over q[0 : TM1*K), MLP=4 -------
        const long long nvec   = NTOT / 4;                 // divisible: K%4==0
        const float4*   q4     = (const float4*)q;
        long long       idx    = (long long)(blockIdx.x - SCAN_BLOCKS) * 32 + threadIdx.x;
        const long long stride = (long long)QSUM_BLOCKS * 32;
        float f0 = 0.0f, f1 = 0.0f, f2 = 0.0f, f3 = 0.0f;
        for (; idx + 3 * stride < nvec; idx += 4 * stride) {
            float4 a = q4[idx];
            float4 b = q4[idx + stride];
            float4 c = q4[idx + 2 * stride];
            float4 d = q4[idx + 3 * stride];
            f0 += sl1(a.x,0.f) + sl1(a.y,0.f) + sl1(a.z,0.f) + sl1(a.w,0.f);
            f1 += sl1(b.x,0.f) + sl1(b.y,0.f) + sl1(b.z,0.f) + sl1(b.w,0.f);
            f2 += sl1(c.x,0.f) + sl1(c.y,0.f) + sl1(c.z,0.f) + sl1(c.w,0.f);
            f3 += sl1(d.x,0.f) + sl1(d.y,0.f) + sl1(d.z,0.f) + sl1(d.w,0.f);
        }
        for (; idx < nvec; idx += stride) {
            float4 a = q4[idx];
            f0 += sl1(a.x,0.f) + sl1(a.y,0.f) + sl1(a.z,0.f) + sl1(a.w,0.f);
        }
        acc = (double)(((f0 + f1) + (f2 + f3)));
    }

    // deterministic warp reduction (fixed shuffle tree)
    #pragma unroll
    for (int off = 16; off > 0; off >>= 1)
        acc += __shfl_xor_sync(0xFFFFFFFFu, acc, off);

    // ---- last-block finalize (fused; deterministic fixed-order final sum) ----
    unsigned int ticket = 0;
    if (threadIdx.x == 0) {
        g_part[blockIdx.x] = acc;
        __threadfence();
        ticket = atomicAdd(&g_done, 1u);
    }
    ticket = __shfl_sync(0xFFFFFFFFu, ticket, 0);
    if (ticket == NBLOCKS - 1) {
        __threadfence();
        double a = 0.0;
        for (int i = threadIdx.x; i < NBLOCKS; i += 32) a += g_part[i];
        #pragma unroll
        for (int off = 16; off > 0; off >>= 1)
            a += __shfl_xor_sync(0xFFFFFFFFu, a, off);
        if (threadIdx.x == 0) {
            out[0]  = (float)(a / (double)NTOT);
            g_done  = 0;                       // reset for next graph replay
        }
    }
}

extern "C" void kernel_launch(void* const* d_in, const int* in_sizes, int n_in,
                              void* d_out, int out_size)
{
    const float* q   = (const float*)d_in[0];  // state_trajectory_action_values (T,K)
    const float* tq  = (const float*)d_in[1];  // target_state_trajectory_action_values (T,K)
    const float* tv  = (const float*)d_in[2];  // target_expected_state_values (T,K)
    const float* r   = (const float*)d_in[3];  // rewards (T,K)
    const float* olp = (const float*)d_in[4];  // original_log_trajectory_action_probs (T,)
    const float* tlp = (const float*)d_in[5];  // target_log_trajectory_task_action_probs (T,K)
    float* out = (float*)d_out;

    retrace_main<<<NBLOCKS, 32>>>(q, tq, tv, r, olp, tlp, out);
}

// round 4
// speedup vs baseline: 7.6353x; 2.7569x over previous
#include <cuda_runtime.h>
#include <cuda_bf16.h>

#define T_DIM 8192
#define K_DIM 2048
#define TM1   (T_DIM - 1)                      // 8191 rows in the loss
#define NTOT  ((long long)TM1 * K_DIM)         // 16,775,168 elements
#define GAMMA 0.99f
#define LOGG  (-0.0100503358535014f)           // logf(0.99)

#define NCHUNK       ((TM1 + 31) / 32)         // 256 row-chunks per column
#define SCAN_BLOCKS  256                       // 256 blocks * 8 warps = 2048 columns
#define QSUM_BLOCKS  296                       // 296 * 256 thr = 2368 warps
#define NBLOCKS      (SCAN_BLOCKS + QSUM_BLOCKS)
#define FULLM        0xFFFFFFFFu

// Scratch (device globals are the allowed scratch mechanism).
// Transposed layout [k][t] so warp-over-rows access is coalesced.
__device__ float2       g_dp  [(long long)K_DIM * TM1];  // {decay, td*decay}
__device__ double       g_part[NBLOCKS];
__device__ unsigned int g_done;                          // zero-init; self-resetting

__device__ __forceinline__ float sl1(float pred, float target) {
    float d  = pred - target;
    float ad = fabsf(d);
    return (ad < 1.0f) ? (0.5f * d * d) : (ad - 0.5f);
}

__global__ void __launch_bounds__(256)
retrace_main(const float* __restrict__ q,
             const float* __restrict__ tq,
             const float* __restrict__ tv,
             const float* __restrict__ r,
             const float* __restrict__ olp,
             const float* __restrict__ tlp,
             float* __restrict__ out)
{
    const int tid  = threadIdx.x;
    const int lane = tid & 31;
    const int wrp  = tid >> 5;
    double acc = 0.0;

    if (blockIdx.x < SCAN_BLOCKS) {
        // ============ one WARP per column; lanes cover 32 consecutive rows ============
        // 8 warps per block cover columns k..k+7 -> together they consume full 32B
        // sectors of the strided row loads (sector = 8 adjacent-k floats).
        const int k = blockIdx.x * 8 + wrp;

        float carry = 0.0f;          // running log(decay) at end of previous chunk
        int   tstop = TM1;           // first row with decay == 0 (exclusive bound)

        // ---- forward: log-space prefix-sum per chunk, double-buffered loads ----
        auto loadch = [&](int cc, float& liw, float& rr, float& tvv, float& tqq) {
            const int  t = cc * 32 + lane;
            const bool v = t < TM1;
            const size_t o1 = (size_t)(t + 1) * K_DIM + k;
            const size_t o0 = (size_t)t       * K_DIM + k;
            liw = v ? (tlp[o1] - olp[t + 1]) : 0.0f;
            rr  = v ? r [o0] : 0.0f;
            tvv = v ? tv[o1] : 0.0f;
            tqq = v ? tq[o1] : 0.0f;
        };
        auto compch = [&](int cc, float liw, float rr, float tvv, float tqq) -> bool {
            const int  t = cc * 32 + lane;
            const bool v = t < TM1;
            float m    = fminf(liw, 0.0f);
            float iw   = expf(m);
            float s    = v ? (LOGG + m) : 0.0f;
            #pragma unroll
            for (int off = 1; off < 32; off <<= 1) {    // inclusive prefix sum
                float u = __shfl_up_sync(FULLM, s, off);
                if (lane >= off) s += u;
            }
            float ls    = carry + s;
            float decay = expf(ls);                      // underflows to exact 0
            float pdv   = (rr + GAMMA * (tvv - iw * tqq)) * decay;
            if (v) g_dp[(size_t)k * TM1 + t] = make_float2(decay, pdv);
            carry = __shfl_sync(FULLM, ls, 31);
            unsigned bal = __ballot_sync(FULLM, v && decay == 0.0f);
            if (bal) { tstop = cc * 32 + (__ffs(bal) - 1); return true; }
            return false;
        };

        {
            float lA, rA, vA, qA, lB, rB, vB, qB;
            loadch(0, lA, rA, vA, qA);
            int  cc = 0;
            while (true) {
                if (cc + 1 < NCHUNK) loadch(cc + 1, lB, rB, vB, qB);
                if (compch(cc, lA, rA, vA, qA)) break;
                if (++cc >= NCHUNK) break;
                if (cc + 1 < NCHUNK) loadch(cc + 1, lA, rA, vA, qA);
                if (compch(cc, lB, rB, vB, qB)) break;
                if (++cc >= NCHUNK) break;
            }
        }

        // ---- backward: warp suffix-sum of pd per chunk, from last active chunk ----
        // Rows in [tstop, chunk_end) were written with decay=0, pd=0 -> retr==0 ->
        // correction exactly 0, so no extra predicate needed beyond t < TM1.
        const int nch = (tstop + 31) >> 5;
        float Rcarry = 0.0f;
        for (int cc = nch - 1; cc >= 0; --cc) {
            const int  t = cc * 32 + lane;
            const bool v = t < TM1;
            float2 dp = v ? g_dp[(size_t)k * TM1 + t] : make_float2(0.0f, 0.0f);
            float  qv = v ? q[(size_t)t * K_DIM + k]  : 0.0f;
            float  s  = dp.y;
            #pragma unroll
            for (int off = 1; off < 32; off <<= 1) {    // inclusive suffix sum
                float u = __shfl_down_sync(FULLM, s, off);
                if (lane + off < 32) s += u;
            }
            float R    = s + Rcarry;                     // sum over all rows >= t
            float retr = R / fmaxf(dp.x, 1e-10f);
            if (v) acc += (double)(sl1(qv, retr) - sl1(qv, 0.0f));
            Rcarry = __shfl_sync(FULLM, R, 0);
        }
    } else {
        // ------- elementwise sum of sl1(q, 0) over q[0 : TM1*K), MLP=4 -------
        const long long nvec   = NTOT / 4;               // divisible: K%4==0
        const float4*   q4     = (const float4*)q;
        long long       idx    = (long long)(blockIdx.x - SCAN_BLOCKS) * 256 + tid;
        const long long stride = (long long)QSUM_BLOCKS * 256;
        float f0 = 0.0f, f1 = 0.0f, f2 = 0.0f, f3 = 0.0f;
        for (; idx + 3 * stride < nvec; idx += 4 * stride) {
            float4 a = q4[idx];
            float4 b = q4[idx + stride];
            float4 c = q4[idx + 2 * stride];
            float4 d = q4[idx + 3 * stride];
            f0 += sl1(a.x,0.f) + sl1(a.y,0.f) + sl1(a.z,0.f) + sl1(a.w,0.f);
            f1 += sl1(b.x,0.f) + sl1(b.y,0.f) + sl1(b.z,0.f) + sl1(b.w,0.f);
            f2 += sl1(c.x,0.f) + sl1(c.y,0.f) + sl1(c.z,0.f) + sl1(c.w,0.f);
            f3 += sl1(d.x,0.f) + sl1(d.y,0.f) + sl1(d.z,0.f) + sl1(d.w,0.f);
        }
        for (; idx < nvec; idx += stride) {
            float4 a = q4[idx];
            f0 += sl1(a.x,0.f) + sl1(a.y,0.f) + sl1(a.z,0.f) + sl1(a.w,0.f);
        }
        acc = (double)((f0 + f1) + (f2 + f3));
    }

    // ---- deterministic block reduction: warp shuffle tree + fixed-order sum ----
    __shared__ double shw[8];
    #pragma unroll
    for (int off = 16; off > 0; off >>= 1)
        acc += __shfl_xor_sync(FULLM, acc, off);
    if (lane == 0) shw[wrp] = acc;
    __syncthreads();
    double blocksum = 0.0;
    if (tid == 0) {
        #pragma unroll
        for (int i = 0; i < 8; ++i) blocksum += shw[i];
    }

    // ---- fused last-block finalize (deterministic fixed-order final sum) ----
    __shared__ unsigned int sticket;
    if (tid == 0) {
        g_part[blockIdx.x] = blocksum;
        __threadfence();
        sticket = atomicAdd(&g_done, 1u);
    }
    __syncthreads();
    if (sticket == NBLOCKS - 1) {
        __threadfence();
        double a = 0.0;
        for (int i = tid; i < NBLOCKS; i += 256) a += g_part[i];
        __shared__ double sh[256];
        sh[tid] = a;
        __syncthreads();
        #pragma unroll
        for (int s = 128; s > 0; s >>= 1) {
            if (tid < s) sh[tid] += sh[tid + s];
            __syncthreads();
        }
        if (tid == 0) {
            out[0] = (float)(sh[0] / (double)NTOT);
            g_done = 0;                        // reset for next graph replay
        }
    }
}

extern "C" void kernel_launch(void* const* d_in, const int* in_sizes, int n_in,
                              void* d_out, int out_size)
{
    const float* q   = (const float*)d_in[0];  // state_trajectory_action_values (T,K)
    const float* tq  = (const float*)d_in[1];  // target_state_trajectory_action_values (T,K)
    const float* tv  = (const float*)d_in[2];  // target_expected_state_values (T,K)
    const float* r   = (const float*)d_in[3];  // rewards (T,K)
    const float* olp = (const float*)d_in[4];  // original_log_trajectory_action_probs (T,)
    const float* tlp = (const float*)d_in[5];  // target_log_trajectory_task_action_probs (T,K)
    float* out = (float*)d_out;

    retrace_main<<<NBLOCKS, 256>>>(q, tq, tv, r, olp, tlp, out);
}